// round 12
// baseline (speedup 1.0000x reference)
#include <cuda_runtime.h>
#include <math.h>

// Problem constants (fixed shapes from reference)
#define B_    4
#define S_    4096
#define H_    16
#define D_    128
#define HALF_ 64
#define MAX_OFFSET_ 512

#define NPAIRS ((B_ * S_) / 2)   // 8192 position-pairs
#define GRID_  444               // 148 SMs * 3 resident blocks (77 regs, 256 thr)

// inv_freq passed by value (constant space), computed on host in double.
struct InvFreq { float v[HALF_]; };

// Persistent one-wave kernel: 444 blocks, grid-stride over 8192 pairs of
// consecutive (b, s) positions. Per iteration each thread front-batches all
// 12 LDG.128 (MLP=12) for float4-pair j of rows r (q), r+16 (k), r+32 (v)
// of both positions, then rotates/stores. Next iteration's loads are
// independent of this iteration's stores -> ptxas can hoist them across the
// store burst, sustaining queue depth through R/W turnarounds.
// cos/sin per position: 2 sincosf + 8 shuffles per thread (identical
// numerics to reference: fp32 inv_freq, fp32 pos*inv, accurate sincosf).
// qkv/out are zero-reuse streams -> evict-first (.cs).
__global__ void __launch_bounds__(256) rope_persist_kernel(
    const float4* __restrict__ qkv,
    const int*    __restrict__ offsets,
    float4*       __restrict__ out,
    InvFreq       inv)
{
    int tid  = threadIdx.x;
    int lane = tid & 31;
    int j    = tid & 15;             // float4 index within the half
    int r    = tid >> 4;             // head row within q-group [0,16)

    float fi_lo = inv.v[2 * lane];
    float fi_hi = inv.v[2 * lane + 1];
    int l0 = 2 * j, l1 = 2 * j + 1;
    int rj = r * 32 + j;             // row-local float4 offset
    const unsigned FULL = 0xFFFFFFFFu;

    for (int pair = blockIdx.x; pair < NPAIRS; pair += GRID_) {
        int bs0 = pair << 1;         // first position; pair never crosses batch

        // float4 offsets: position block = 48 rows * 32 float4 = 1536
        int qoff0 = bs0 * 1536 + rj;         // q row, pos0
        int koff0 = qoff0 + 512;             // +16*32
        int voff0 = qoff0 + 1024;            // +32*32
        int qoff1 = qoff0 + 1536;
        int koff1 = koff0 + 1536;
        int voff1 = voff0 + 1536;

        // Front-batch all 12 loads (MLP=12) before any math
        float4 q1a = __ldcs(&qkv[qoff0]);
        float4 q2a = __ldcs(&qkv[qoff0 + 16]);
        float4 k1a = __ldcs(&qkv[koff0]);
        float4 k2a = __ldcs(&qkv[koff0 + 16]);
        float4 v1a = __ldcs(&qkv[voff0]);
        float4 v2a = __ldcs(&qkv[voff0 + 16]);
        float4 q1b = __ldcs(&qkv[qoff1]);
        float4 q2b = __ldcs(&qkv[qoff1 + 16]);
        float4 k1b = __ldcs(&qkv[koff1]);
        float4 k2b = __ldcs(&qkv[koff1 + 16]);
        float4 v1b = __ldcs(&qkv[voff1]);
        float4 v2b = __ldcs(&qkv[voff1 + 16]);

        int b    = bs0 >> 12;        // S = 4096
        int s0   = bs0 & (S_ - 1);
        float fpos = (float)(offsets[b] + s0);

        float4 o1, o2;

        // ---- position 0 ----
        {
            float c_lo, s_lo, c_hi, s_hi;
            sincosf(fpos * fi_lo, &s_lo, &c_lo);
            sincosf(fpos * fi_hi, &s_hi, &c_hi);
            float4 c, sn;
            c.x  = __shfl_sync(FULL, c_lo, l0);
            c.y  = __shfl_sync(FULL, c_hi, l0);
            c.z  = __shfl_sync(FULL, c_lo, l1);
            c.w  = __shfl_sync(FULL, c_hi, l1);
            sn.x = __shfl_sync(FULL, s_lo, l0);
            sn.y = __shfl_sync(FULL, s_hi, l0);
            sn.z = __shfl_sync(FULL, s_lo, l1);
            sn.w = __shfl_sync(FULL, s_hi, l1);

            o1.x = fmaf(q1a.x, c.x, -q2a.x * sn.x);
            o1.y = fmaf(q1a.y, c.y, -q2a.y * sn.y);
            o1.z = fmaf(q1a.z, c.z, -q2a.z * sn.z);
            o1.w = fmaf(q1a.w, c.w, -q2a.w * sn.w);
            o2.x = fmaf(q1a.x, sn.x, q2a.x * c.x);
            o2.y = fmaf(q1a.y, sn.y, q2a.y * c.y);
            o2.z = fmaf(q1a.z, sn.z, q2a.z * c.z);
            o2.w = fmaf(q1a.w, sn.w, q2a.w * c.w);
            __stcs(&out[qoff0],      o1);
            __stcs(&out[qoff0 + 16], o2);

            o1.x = fmaf(k1a.x, c.x, -k2a.x * sn.x);
            o1.y = fmaf(k1a.y, c.y, -k2a.y * sn.y);
            o1.z = fmaf(k1a.z, c.z, -k2a.z * sn.z);
            o1.w = fmaf(k1a.w, c.w, -k2a.w * sn.w);
            o2.x = fmaf(k1a.x, sn.x, k2a.x * c.x);
            o2.y = fmaf(k1a.y, sn.y, k2a.y * c.y);
            o2.z = fmaf(k1a.z, sn.z, k2a.z * c.z);
            o2.w = fmaf(k1a.w, sn.w, k2a.w * c.w);
            __stcs(&out[koff0],      o1);
            __stcs(&out[koff0 + 16], o2);

            __stcs(&out[voff0],      v1a);
            __stcs(&out[voff0 + 16], v2a);
        }

        // ---- position 1 ----
        {
            float fp1 = fpos + 1.0f;
            float c_lo, s_lo, c_hi, s_hi;
            sincosf(fp1 * fi_lo, &s_lo, &c_lo);
            sincosf(fp1 * fi_hi, &s_hi, &c_hi);
            float4 c, sn;
            c.x  = __shfl_sync(FULL, c_lo, l0);
            c.y  = __shfl_sync(FULL, c_hi, l0);
            c.z  = __shfl_sync(FULL, c_lo, l1);
            c.w  = __shfl_sync(FULL, c_hi, l1);
            sn.x = __shfl_sync(FULL, s_lo, l0);
            sn.y = __shfl_sync(FULL, s_hi, l0);
            sn.z = __shfl_sync(FULL, s_lo, l1);
            sn.w = __shfl_sync(FULL, s_hi, l1);

            o1.x = fmaf(q1b.x, c.x, -q2b.x * sn.x);
            o1.y = fmaf(q1b.y, c.y, -q2b.y * sn.y);
            o1.z = fmaf(q1b.z, c.z, -q2b.z * sn.z);
            o1.w = fmaf(q1b.w, c.w, -q2b.w * sn.w);
            o2.x = fmaf(q1b.x, sn.x, q2b.x * c.x);
            o2.y = fmaf(q1b.y, sn.y, q2b.y * c.y);
            o2.z = fmaf(q1b.z, sn.z, q2b.z * c.z);
            o2.w = fmaf(q1b.w, sn.w, q2b.w * c.w);
            __stcs(&out[qoff1],      o1);
            __stcs(&out[qoff1 + 16], o2);

            o1.x = fmaf(k1b.x, c.x, -k2b.x * sn.x);
            o1.y = fmaf(k1b.y, c.y, -k2b.y * sn.y);
            o1.z = fmaf(k1b.z, c.z, -k2b.z * sn.z);
            o1.w = fmaf(k1b.w, c.w, -k2b.w * sn.w);
            o2.x = fmaf(k1b.x, sn.x, k2b.x * c.x);
            o2.y = fmaf(k1b.y, sn.y, k2b.y * c.y);
            o2.z = fmaf(k1b.z, sn.z, k2b.z * c.z);
            o2.w = fmaf(k1b.w, sn.w, k2b.w * c.w);
            __stcs(&out[koff1],      o1);
            __stcs(&out[koff1 + 16], o2);

            __stcs(&out[voff1],      v1b);
            __stcs(&out[voff1 + 16], v2b);
        }
    }
}

extern "C" void kernel_launch(void* const* d_in, const int* in_sizes, int n_in,
                              void* d_out, int out_size) {
    const float4* qkv     = (const float4*)d_in[0];
    const int*    offsets = (const int*)d_in[1];
    float4*       out     = (float4*)d_out;

    // Host-side inv_freq: double precision, rounded to fp32 (same numerics
    // as before). Deterministic; 64 floats passed by value.
    InvFreq inv;
    for (int i = 0; i < HALF_; i++) {
        inv.v[i] = (float)exp(-log(10000.0) * ((double)i / 64.0));
    }

    rope_persist_kernel<<<GRID_, 256>>>(qkv, offsets, out, inv);
}

// round 13
// speedup vs baseline: 1.1009x; 1.1009x over previous
#include <cuda_runtime.h>
#include <math.h>

// Problem constants (fixed shapes from reference)
#define B_    4
#define S_    4096
#define H_    16
#define D_    128
#define HALF_ 64
#define MAX_OFFSET_ 512

// inv_freq passed by value (constant space), computed on host in double.
struct InvFreq { float v[HALF_]; };

// One block per TWO consecutive (b, s) positions (R10 structure — measured
// best: 85.1% DRAM / 6742 GB/s). 256 threads, no smem/sync. Each thread owns
// float4-pair j = tid&15 of rows r (q), r+16 (k), r+32 (v), r = tid>>4, for
// BOTH positions: 12 front-batched LDG.128 (MLP=12).
// Micro-reorder vs R10: the 4 v-copy stores (load-dependent only) issue
// IMMEDIATELY after the loads, overlapping the store path with the ~40cyc
// sincos+shuffle latency chain instead of bunching all stores at the end.
// cos/sin per position: 2 sincosf + 8 shuffles (identical numerics to
// reference: fp32 inv_freq, fp32 pos*inv, accurate sincosf).
// qkv/out are zero-reuse streams -> evict-first (.cs).
__global__ void __launch_bounds__(256) rope_fused2_kernel(
    const float4* __restrict__ qkv,
    const int*    __restrict__ offsets,
    float4*       __restrict__ out,
    InvFreq       inv)
{
    int bs0  = blockIdx.x << 1;      // first position (b*S + s), pair-aligned
    int tid  = threadIdx.x;
    int lane = tid & 31;
    int j    = tid & 15;             // float4 index within the half
    int r    = tid >> 4;             // head row within q-group [0,16)

    // float4 offsets: position block = 48 rows * 32 float4 = 1536
    // max index = 16384*1536 + 1535 < 2^31 -> 32-bit indexing is safe.
    int qoff0 = bs0 * 1536 + r * 32 + j;  // q row, pos0
    int koff0 = qoff0 + 16 * 32;          // k row
    int voff0 = qoff0 + 32 * 32;          // v row
    int qoff1 = qoff0 + 1536;             // same rows, pos1
    int koff1 = koff0 + 1536;
    int voff1 = voff0 + 1536;

    // Front-batch all 12 loads (MLP=12) before any math
    float4 q1a = __ldcs(&qkv[qoff0]);
    float4 q2a = __ldcs(&qkv[qoff0 + 16]);
    float4 k1a = __ldcs(&qkv[koff0]);
    float4 k2a = __ldcs(&qkv[koff0 + 16]);
    float4 v1a = __ldcs(&qkv[voff0]);
    float4 v2a = __ldcs(&qkv[voff0 + 16]);
    float4 q1b = __ldcs(&qkv[qoff1]);
    float4 q2b = __ldcs(&qkv[qoff1 + 16]);
    float4 k1b = __ldcs(&qkv[koff1]);
    float4 k2b = __ldcs(&qkv[koff1 + 16]);
    float4 v1b = __ldcs(&qkv[voff1]);
    float4 v2b = __ldcs(&qkv[voff1 + 16]);

    // v copies depend only on loads: issue these stores NOW so they drain
    // while the sincos/shuffle chain below is in flight.
    __stcs(&out[voff0],      v1a);
    __stcs(&out[voff0 + 16], v2a);
    __stcs(&out[voff1],      v1b);
    __stcs(&out[voff1 + 16], v2b);

    // Position bases
    int b    = bs0 >> 12;            // S = 4096; pair never crosses a batch
    int s0   = bs0 & (S_ - 1);
    int pos0 = offsets[b] + s0;

    const unsigned FULL = 0xFFFFFFFFu;
    int l0 = 2 * j, l1 = 2 * j + 1;
    float fi_lo = inv.v[2 * lane];
    float fi_hi = inv.v[2 * lane + 1];

    float4 o1, o2;

    // ---- position 0 ----
    {
        float fpos = (float)pos0;
        float c_lo, s_lo, c_hi, s_hi;
        sincosf(fpos * fi_lo, &s_lo, &c_lo);
        sincosf(fpos * fi_hi, &s_hi, &c_hi);
        float4 c, sn;
        c.x  = __shfl_sync(FULL, c_lo, l0);
        c.y  = __shfl_sync(FULL, c_hi, l0);
        c.z  = __shfl_sync(FULL, c_lo, l1);
        c.w  = __shfl_sync(FULL, c_hi, l1);
        sn.x = __shfl_sync(FULL, s_lo, l0);
        sn.y = __shfl_sync(FULL, s_hi, l0);
        sn.z = __shfl_sync(FULL, s_lo, l1);
        sn.w = __shfl_sync(FULL, s_hi, l1);

        o1.x = fmaf(q1a.x, c.x, -q2a.x * sn.x);
        o1.y = fmaf(q1a.y, c.y, -q2a.y * sn.y);
        o1.z = fmaf(q1a.z, c.z, -q2a.z * sn.z);
        o1.w = fmaf(q1a.w, c.w, -q2a.w * sn.w);
        o2.x = fmaf(q1a.x, sn.x, q2a.x * c.x);
        o2.y = fmaf(q1a.y, sn.y, q2a.y * c.y);
        o2.z = fmaf(q1a.z, sn.z, q2a.z * c.z);
        o2.w = fmaf(q1a.w, sn.w, q2a.w * c.w);
        __stcs(&out[qoff0],      o1);
        __stcs(&out[qoff0 + 16], o2);

        o1.x = fmaf(k1a.x, c.x, -k2a.x * sn.x);
        o1.y = fmaf(k1a.y, c.y, -k2a.y * sn.y);
        o1.z = fmaf(k1a.z, c.z, -k2a.z * sn.z);
        o1.w = fmaf(k1a.w, c.w, -k2a.w * sn.w);
        o2.x = fmaf(k1a.x, sn.x, k2a.x * c.x);
        o2.y = fmaf(k1a.y, sn.y, k2a.y * c.y);
        o2.z = fmaf(k1a.z, sn.z, k2a.z * c.z);
        o2.w = fmaf(k1a.w, sn.w, k2a.w * c.w);
        __stcs(&out[koff0],      o1);
        __stcs(&out[koff0 + 16], o2);
    }

    // ---- position 1 ----
    {
        float fpos = (float)(pos0 + 1);
        float c_lo, s_lo, c_hi, s_hi;
        sincosf(fpos * fi_lo, &s_lo, &c_lo);
        sincosf(fpos * fi_hi, &s_hi, &c_hi);
        float4 c, sn;
        c.x  = __shfl_sync(FULL, c_lo, l0);
        c.y  = __shfl_sync(FULL, c_hi, l0);
        c.z  = __shfl_sync(FULL, c_lo, l1);
        c.w  = __shfl_sync(FULL, c_hi, l1);
        sn.x = __shfl_sync(FULL, s_lo, l0);
        sn.y = __shfl_sync(FULL, s_hi, l0);
        sn.z = __shfl_sync(FULL, s_lo, l1);
        sn.w = __shfl_sync(FULL, s_hi, l1);

        o1.x = fmaf(q1b.x, c.x, -q2b.x * sn.x);
        o1.y = fmaf(q1b.y, c.y, -q2b.y * sn.y);
        o1.z = fmaf(q1b.z, c.z, -q2b.z * sn.z);
        o1.w = fmaf(q1b.w, c.w, -q2b.w * sn.w);
        o2.x = fmaf(q1b.x, sn.x, q2b.x * c.x);
        o2.y = fmaf(q1b.y, sn.y, q2b.y * c.y);
        o2.z = fmaf(q1b.z, sn.z, q2b.z * c.z);
        o2.w = fmaf(q1b.w, sn.w, q2b.w * c.w);
        __stcs(&out[qoff1],      o1);
        __stcs(&out[qoff1 + 16], o2);

        o1.x = fmaf(k1b.x, c.x, -k2b.x * sn.x);
        o1.y = fmaf(k1b.y, c.y, -k2b.y * sn.y);
        o1.z = fmaf(k1b.z, c.z, -k2b.z * sn.z);
        o1.w = fmaf(k1b.w, c.w, -k2b.w * sn.w);
        o2.x = fmaf(k1b.x, sn.x, k2b.x * c.x);
        o2.y = fmaf(k1b.y, sn.y, k2b.y * c.y);
        o2.z = fmaf(k1b.z, sn.z, k2b.z * c.z);
        o2.w = fmaf(k1b.w, sn.w, k2b.w * c.w);
        __stcs(&out[koff1],      o1);
        __stcs(&out[koff1 + 16], o2);
    }
}

extern "C" void kernel_launch(void* const* d_in, const int* in_sizes, int n_in,
                              void* d_out, int out_size) {
    const float4* qkv     = (const float4*)d_in[0];
    const int*    offsets = (const int*)d_in[1];
    float4*       out     = (float4*)d_out;

    // Host-side inv_freq: double precision, rounded to fp32 (same numerics
    // as before). Deterministic; 64 floats passed by value.
    InvFreq inv;
    for (int i = 0; i < HALF_; i++) {
        inv.v[i] = (float)exp(-log(10000.0) * ((double)i / 64.0));
    }

    rope_fused2_kernel<<<(B_ * S_) / 2, 256>>>(qkv, offsets, out, inv);
}

// round 14
// speedup vs baseline: 1.1077x; 1.0062x over previous
#include <cuda_runtime.h>
#include <math.h>

// Problem constants (fixed shapes from reference)
#define B_    4
#define S_    4096
#define H_    16
#define D_    128
#define HALF_ 64
#define MAX_OFFSET_ 512

// inv_freq passed by value (constant space), computed on host in double.
struct InvFreq { float v[HALF_]; };

// MEASURED-BEST configuration (R10): one block per TWO consecutive (b, s)
// positions. 256 threads, no smem, no __syncthreads. Each thread owns
// float4-pair j = tid&15 of rows r (q), r+16 (k), r+32 (v), r = tid>>4, for
// BOTH positions: 12 front-batched LDG.128 (MLP=12), then sincos, then all
// stores batched at the end. Perturbations in either direction (deeper
// pipelining, earlier stores, persistence) all measured worse — this
// load-burst/store-burst schedule maximizes DRAM R/W-turnaround amortization
// (85.1% DRAM, 6742 GB/s).
// cos/sin per position: 2 sincosf + 8 shuffles per thread (identical
// numerics to reference: fp32 inv_freq, fp32 pos*inv, accurate sincosf).
// qkv/out are zero-reuse streams -> evict-first (.cs).
__global__ void __launch_bounds__(256) rope_fused2_kernel(
    const float4* __restrict__ qkv,
    const int*    __restrict__ offsets,
    float4*       __restrict__ out,
    InvFreq       inv)
{
    int bs0  = blockIdx.x << 1;      // first position (b*S + s), pair-aligned
    int tid  = threadIdx.x;
    int lane = tid & 31;
    int j    = tid & 15;             // float4 index within the half
    int r    = tid >> 4;             // head row within q-group [0,16)

    // float4 offsets: position block = 48 rows * 32 float4 = 1536
    // max index = 16384*1536 + 1535 < 2^31 -> 32-bit indexing is safe.
    int qoff0 = bs0 * 1536 + r * 32 + j;  // q row, pos0
    int koff0 = qoff0 + 16 * 32;          // k row
    int voff0 = qoff0 + 32 * 32;          // v row
    int qoff1 = qoff0 + 1536;             // same rows, pos1
    int koff1 = koff0 + 1536;
    int voff1 = voff0 + 1536;

    // Front-batch all 12 loads (MLP=12) before any math
    float4 q1a = __ldcs(&qkv[qoff0]);
    float4 q2a = __ldcs(&qkv[qoff0 + 16]);
    float4 k1a = __ldcs(&qkv[koff0]);
    float4 k2a = __ldcs(&qkv[koff0 + 16]);
    float4 v1a = __ldcs(&qkv[voff0]);
    float4 v2a = __ldcs(&qkv[voff0 + 16]);
    float4 q1b = __ldcs(&qkv[qoff1]);
    float4 q2b = __ldcs(&qkv[qoff1 + 16]);
    float4 k1b = __ldcs(&qkv[koff1]);
    float4 k2b = __ldcs(&qkv[koff1 + 16]);
    float4 v1b = __ldcs(&qkv[voff1]);
    float4 v2b = __ldcs(&qkv[voff1 + 16]);

    // Position bases
    int b    = bs0 >> 12;            // S = 4096; pair never crosses a batch
    int s0   = bs0 & (S_ - 1);
    int pos0 = offsets[b] + s0;

    const unsigned FULL = 0xFFFFFFFFu;
    int l0 = 2 * j, l1 = 2 * j + 1;
    float fi_lo = inv.v[2 * lane];
    float fi_hi = inv.v[2 * lane + 1];

    float4 o1, o2;

    // ---- position 0 ----
    {
        float fpos = (float)pos0;
        float c_lo, s_lo, c_hi, s_hi;
        sincosf(fpos * fi_lo, &s_lo, &c_lo);
        sincosf(fpos * fi_hi, &s_hi, &c_hi);
        float4 c, sn;
        c.x  = __shfl_sync(FULL, c_lo, l0);
        c.y  = __shfl_sync(FULL, c_hi, l0);
        c.z  = __shfl_sync(FULL, c_lo, l1);
        c.w  = __shfl_sync(FULL, c_hi, l1);
        sn.x = __shfl_sync(FULL, s_lo, l0);
        sn.y = __shfl_sync(FULL, s_hi, l0);
        sn.z = __shfl_sync(FULL, s_lo, l1);
        sn.w = __shfl_sync(FULL, s_hi, l1);

        o1.x = fmaf(q1a.x, c.x, -q2a.x * sn.x);
        o1.y = fmaf(q1a.y, c.y, -q2a.y * sn.y);
        o1.z = fmaf(q1a.z, c.z, -q2a.z * sn.z);
        o1.w = fmaf(q1a.w, c.w, -q2a.w * sn.w);
        o2.x = fmaf(q1a.x, sn.x, q2a.x * c.x);
        o2.y = fmaf(q1a.y, sn.y, q2a.y * c.y);
        o2.z = fmaf(q1a.z, sn.z, q2a.z * c.z);
        o2.w = fmaf(q1a.w, sn.w, q2a.w * c.w);
        __stcs(&out[qoff0],      o1);
        __stcs(&out[qoff0 + 16], o2);

        o1.x = fmaf(k1a.x, c.x, -k2a.x * sn.x);
        o1.y = fmaf(k1a.y, c.y, -k2a.y * sn.y);
        o1.z = fmaf(k1a.z, c.z, -k2a.z * sn.z);
        o1.w = fmaf(k1a.w, c.w, -k2a.w * sn.w);
        o2.x = fmaf(k1a.x, sn.x, k2a.x * c.x);
        o2.y = fmaf(k1a.y, sn.y, k2a.y * c.y);
        o2.z = fmaf(k1a.z, sn.z, k2a.z * c.z);
        o2.w = fmaf(k1a.w, sn.w, k2a.w * c.w);
        __stcs(&out[koff0],      o1);
        __stcs(&out[koff0 + 16], o2);

        __stcs(&out[voff0],      v1a);
        __stcs(&out[voff0 + 16], v2a);
    }

    // ---- position 1 ----
    {
        float fpos = (float)(pos0 + 1);
        float c_lo, s_lo, c_hi, s_hi;
        sincosf(fpos * fi_lo, &s_lo, &c_lo);
        sincosf(fpos * fi_hi, &s_hi, &c_hi);
        float4 c, sn;
        c.x  = __shfl_sync(FULL, c_lo, l0);
        c.y  = __shfl_sync(FULL, c_hi, l0);
        c.z  = __shfl_sync(FULL, c_lo, l1);
        c.w  = __shfl_sync(FULL, c_hi, l1);
        sn.x = __shfl_sync(FULL, s_lo, l0);
        sn.y = __shfl_sync(FULL, s_hi, l0);
        sn.z = __shfl_sync(FULL, s_lo, l1);
        sn.w = __shfl_sync(FULL, s_hi, l1);

        o1.x = fmaf(q1b.x, c.x, -q2b.x * sn.x);
        o1.y = fmaf(q1b.y, c.y, -q2b.y * sn.y);
        o1.z = fmaf(q1b.z, c.z, -q2b.z * sn.z);
        o1.w = fmaf(q1b.w, c.w, -q2b.w * sn.w);
        o2.x = fmaf(q1b.x, sn.x, q2b.x * c.x);
        o2.y = fmaf(q1b.y, sn.y, q2b.y * c.y);
        o2.z = fmaf(q1b.z, sn.z, q2b.z * c.z);
        o2.w = fmaf(q1b.w, sn.w, q2b.w * c.w);
        __stcs(&out[qoff1],      o1);
        __stcs(&out[qoff1 + 16], o2);

        o1.x = fmaf(k1b.x, c.x, -k2b.x * sn.x);
        o1.y = fmaf(k1b.y, c.y, -k2b.y * sn.y);
        o1.z = fmaf(k1b.z, c.z, -k2b.z * sn.z);
        o1.w = fmaf(k1b.w, c.w, -k2b.w * sn.w);
        o2.x = fmaf(k1b.x, sn.x, k2b.x * c.x);
        o2.y = fmaf(k1b.y, sn.y, k2b.y * c.y);
        o2.z = fmaf(k1b.z, sn.z, k2b.z * c.z);
        o2.w = fmaf(k1b.w, sn.w, k2b.w * c.w);
        __stcs(&out[koff1],      o1);
        __stcs(&out[koff1 + 16], o2);

        __stcs(&out[voff1],      v1b);
        __stcs(&out[voff1 + 16], v2b);
    }
}

extern "C" void kernel_launch(void* const* d_in, const int* in_sizes, int n_in,
                              void* d_out, int out_size) {
    const float4* qkv     = (const float4*)d_in[0];
    const int*    offsets = (const int*)d_in[1];
    float4*       out     = (float4*)d_out;

    // Host-side inv_freq: double precision, rounded to fp32 (same numerics
    // as before). Deterministic; 64 floats passed by value.
    InvFreq inv;
    for (int i = 0; i < HALF_; i++) {
        inv.v[i] = (float)exp(-log(10000.0) * ((double)i / 64.0));
    }

    rope_fused2_kernel<<<(B_ * S_) / 2, 256>>>(qkv, offsets, out, inv);
}